// round 14
// baseline (speedup 1.0000x reference)
#include <cuda_runtime.h>
#include <cuda_bf16.h>
#include <cstdint>

#define NB 32
#define NS 4096
#define NH 256
#define ND 512
#define BM 128
#define CH 64                    // B k-slice
#define NSL (ND/CH)              // 8 slices

#define ROWA 520                 // A smem row stride (elems): 512+8 pad, ldmatrix conflict-free
#define ROWB 72                  // B smem row stride (elems): 64+8 pad, 144B => 4r mod 32 banks
#define SM_A_BYTES (BM*ROWA*2)           // 133120
#define SM_B_BYTES (128*ROWB*2)          // 18432 per buffer
#define OFF_A   0
#define OFF_B   (SM_A_BYTES)             // 133120 (16B aligned)
#define OFF_DEC (OFF_B + 2*SM_B_BYTES)   // 169984
#define OFF_WC  (OFF_DEC + ND*4)
#define OFF_V   (OFF_WC  + ND*4)
#define OFF_COV (OFF_V   + ND*4)
#define OFF_SC  (OFF_COV + BM*4)
#define SMEM_TOTAL (OFF_SC + BM*4)       // 177152 bytes

// scratch (no allocations allowed -> device globals)
__device__ float g_score[NB*NS];
__device__ float g_dec[NB*ND];
__device__ __align__(16) __nv_bfloat16 g_wh[ND*ND];

__device__ __forceinline__ float tanh_apx(float x){
    float y; asm("tanh.approx.f32 %0, %1;" : "=f"(y) : "f"(x)); return y;
}

// ---------------- kernel 1: prep (Wh->bf16 + dec_feat) ----------------
__global__ void k_prep(const float* __restrict__ wh, const float* __restrict__ hdec,
                       const float* __restrict__ cdec, const float* __restrict__ Ws,
                       const float* __restrict__ Wsb){
    if (blockIdx.x < 512){
        int i = blockIdx.x*512 + threadIdx.x;        // 512 blocks cover D*D
        g_wh[i] = __float2bfloat16(wh[i]);
    } else {
        int b = blockIdx.x - 512, e = threadIdx.x;   // 32 blocks x 512 threads
        __shared__ float st[ND];
        st[e] = (e < NH) ? hdec[b*NH + e] : cdec[b*NH + e - NH];
        __syncthreads();
        const float4* w4 = reinterpret_cast<const float4*>(Ws + (size_t)e*ND);
        float acc = 0.f;
#pragma unroll 16
        for (int d4 = 0; d4 < ND/4; ++d4){
            float4 w = w4[d4];
            acc += st[4*d4]*w.x + st[4*d4+1]*w.y + st[4*d4+2]*w.z + st[4*d4+3]*w.w;
        }
        g_dec[b*ND + e] = acc + Wsb[e];
    }
}

// ---------------- kernel 2: fused score GEMM (mma.sync, 16 warps) ----------------
// score[b,s] = sum_e v[e]*tanh( (enc@Wh^T)[b,s,e] + dec[b,e] + cov[b,s]*wc[e] )
__global__ void __launch_bounds__(512, 1)
k_score(const float* __restrict__ enc, const float* __restrict__ cov,
        const float* __restrict__ wc, const float* __restrict__ vw){
    extern __shared__ char smem[];
    const int tid   = threadIdx.x;
    const int lane  = tid & 31;
    const int warp  = tid >> 5;
    const int warpM = warp >> 2;     // 0..3 (32 rows each)
    const int warpN = warp & 3;      // 0..3 (32 cols each of the 128-col n-chunk)
    const int b  = blockIdx.y;
    const int s0 = blockIdx.x * BM;

    float* dec_s = (float*)(smem + OFF_DEC);
    float* wc_s  = (float*)(smem + OFF_WC);
    float* v_s   = (float*)(smem + OFF_V);
    float* cov_s = (float*)(smem + OFF_COV);
    float* sc_s  = (float*)(smem + OFF_SC);

    if (tid < ND){ dec_s[tid] = g_dec[b*ND + tid]; wc_s[tid] = wc[tid]; v_s[tid] = vw[tid]; }
    if (tid < BM){ cov_s[tid] = cov[(size_t)b*NS + s0 + tid]; sc_s[tid] = 0.f; }

    const uint32_t aBase = (uint32_t)__cvta_generic_to_shared(smem + OFF_A);
    const uint32_t bBase = (uint32_t)__cvta_generic_to_shared(smem + OFF_B);
    const float4*  enc4  = reinterpret_cast<const float4*>(enc);

    // per-thread ldmatrix element offsets (m8n8.x4, both K-major)
    int aOff[2];
#pragma unroll
    for (int mt = 0; mt < 2; ++mt)
        aOff[mt] = (warpM*32 + mt*16 + (lane & 15))*ROWA + (lane >> 4)*8;
    int bOff[2];
#pragma unroll
    for (int np = 0; np < 2; ++np)
        bOff[np] = (warpN*32 + np*16 + ((lane >> 4) & 1)*8 + (lane & 7))*ROWB
                   + ((lane >> 3) & 1)*8;

    // A-convert helper indices (4 float4 per thread per 64-k slice)
    const int ar = tid >> 4;          // row for t=0 (rows advance by 32 per t)
    const int aq = tid & 15;          // float4 index within slice

    // ---- prologue: A slice 0 convert+store; B slice 0 cp.async ----
    {
#pragma unroll
        for (int t = 0; t < 4; ++t){
            int r = ar + t*32;
            float4 f = enc4[((size_t)(b*NS + s0 + r))*(ND/4) + aq];
            __nv_bfloat162 lo = __floats2bfloat162_rn(f.x, f.y);
            __nv_bfloat162 hi = __floats2bfloat162_rn(f.z, f.w);
            uint2 u; u.x = *reinterpret_cast<uint32_t*>(&lo); u.y = *reinterpret_cast<uint32_t*>(&hi);
            *reinterpret_cast<uint2*>(smem + OFF_A + r*(ROWA*2) + aq*8) = u;
        }
#pragma unroll
        for (int j = 0; j < 2; ++j){
            int cid = tid + j*512;
            int row = cid >> 3, chk = cid & 7;
            const __nv_bfloat16* src = g_wh + (size_t)row*ND + chk*8;
            uint32_t dst = bBase + row*(ROWB*2) + chk*16;
            asm volatile("cp.async.cg.shared.global [%0], [%1], 16;\n"
                         :: "r"(dst), "l"(src) : "memory");
        }
        asm volatile("cp.async.commit_group;\n" ::: "memory");
    }

    float rsum[4];
#pragma unroll
    for (int j = 0; j < 4; ++j) rsum[j] = 0.f;

#pragma unroll 1
    for (int nc = 0; nc < 4; ++nc){
        const int n0 = nc*128;
        float c[8][4];
#pragma unroll
        for (int t = 0; t < 8; ++t){ c[t][0]=0.f;c[t][1]=0.f;c[t][2]=0.f;c[t][3]=0.f; }

#pragma unroll 1
        for (int sl = 0; sl < NSL; ++sl){
            // issue B cp.async for next slice (wraps into next n-chunk's slice 0)
            const bool more = (nc < 3) || (sl < 7);
            if (more){
                int nn = (sl == 7) ? (n0 + 128) : n0;
                int kk = (sl == 7) ? 0 : (sl + 1)*CH;
                uint32_t bufOff = ((sl + 1) & 1) * SM_B_BYTES;
#pragma unroll
                for (int j = 0; j < 2; ++j){
                    int cid = tid + j*512;
                    int row = cid >> 3, chk = cid & 7;
                    const __nv_bfloat16* src = g_wh + (size_t)(nn + row)*ND + kk + chk*8;
                    uint32_t dst = bBase + bufOff + row*(ROWB*2) + chk*16;
                    asm volatile("cp.async.cg.shared.global [%0], [%1], 16;\n"
                                 :: "r"(dst), "l"(src) : "memory");
                }
                asm volatile("cp.async.commit_group;\n" ::: "memory");
                asm volatile("cp.async.wait_group 1;\n" ::: "memory");
            } else {
                asm volatile("cp.async.wait_group 0;\n" ::: "memory");
            }
            __syncthreads();   // B slice sl ready; A slice sl ready (nc==0)

            // prefetch A slice sl+1 (first n-chunk only): LDG issues before MMA block
            float4 apre[4];
            const bool aload = (nc == 0) && (sl < 7);
            if (aload){
#pragma unroll
                for (int t = 0; t < 4; ++t){
                    int r = ar + t*32;
                    apre[t] = enc4[((size_t)(b*NS + s0 + r))*(ND/4) + (sl+1)*16 + aq];
                }
            }

            const uint32_t bBuf = bBase + (uint32_t)(sl & 1)*SM_B_BYTES;
#pragma unroll
            for (int k2 = 0; k2 < 4; ++k2){
                const int kkA = sl*CH + k2*16;
                uint32_t a[2][4], bb[2][4];
#pragma unroll
                for (int mt = 0; mt < 2; ++mt){
                    uint32_t addr = aBase + (uint32_t)(aOff[mt] + kkA)*2;
                    asm volatile("ldmatrix.sync.aligned.m8n8.x4.shared.b16 {%0,%1,%2,%3}, [%4];\n"
                        : "=r"(a[mt][0]), "=r"(a[mt][1]), "=r"(a[mt][2]), "=r"(a[mt][3])
                        : "r"(addr));
                }
#pragma unroll
                for (int np = 0; np < 2; ++np){
                    uint32_t addr = bBuf + (uint32_t)(bOff[np] + k2*16)*2;
                    asm volatile("ldmatrix.sync.aligned.m8n8.x4.shared.b16 {%0,%1,%2,%3}, [%4];\n"
                        : "=r"(bb[np][0]), "=r"(bb[np][1]), "=r"(bb[np][2]), "=r"(bb[np][3])
                        : "r"(addr));
                }
#pragma unroll
                for (int mt = 0; mt < 2; ++mt){
#pragma unroll
                    for (int nt = 0; nt < 4; ++nt){
                        float* cc = c[mt*4 + nt];
                        uint32_t b0 = bb[nt>>1][(nt&1)*2], b1 = bb[nt>>1][(nt&1)*2 + 1];
                        asm("mma.sync.aligned.m16n8k16.row.col.f32.bf16.bf16.f32 "
                            "{%0,%1,%2,%3}, {%4,%5,%6,%7}, {%8,%9}, {%0,%1,%2,%3};\n"
                            : "+f"(cc[0]), "+f"(cc[1]), "+f"(cc[2]), "+f"(cc[3])
                            : "r"(a[mt][0]), "r"(a[mt][1]), "r"(a[mt][2]), "r"(a[mt][3]),
                              "r"(b0), "r"(b1));
                    }
                }
            }

            if (aload){
#pragma unroll
                for (int t = 0; t < 4; ++t){
                    int r = ar + t*32;
                    __nv_bfloat162 lo = __floats2bfloat162_rn(apre[t].x, apre[t].y);
                    __nv_bfloat162 hi = __floats2bfloat162_rn(apre[t].z, apre[t].w);
                    uint2 u; u.x = *reinterpret_cast<uint32_t*>(&lo); u.y = *reinterpret_cast<uint32_t*>(&hi);
                    *reinterpret_cast<uint2*>(smem + OFF_A + r*(ROWA*2) + ((sl+1)*CH + aq*4)*2) = u;
                }
            }
            __syncthreads();   // B buf (sl&1) free for reuse; A slice sl+1 visible
        }

        // ---- fused epilogue for this 128-col n-chunk ----
        const int rq = lane >> 2;            // 0..7
        const int eq = (lane & 3)*2;
#pragma unroll
        for (int mt = 0; mt < 2; ++mt){
            int rlo = warpM*32 + mt*16 + rq;
            float cvL = cov_s[rlo], cvH = cov_s[rlo + 8];
#pragma unroll
            for (int nt = 0; nt < 4; ++nt){
                int e0 = n0 + warpN*32 + nt*8 + eq;
                float d0 = dec_s[e0], d1 = dec_s[e0+1];
                float w0 = wc_s[e0],  w1 = wc_s[e0+1];
                float v0 = v_s[e0],   v1 = v_s[e0+1];
                float* cc = c[mt*4 + nt];
                float t0 = tanh_apx(cc[0] + d0 + cvL*w0);
                float t1 = tanh_apx(cc[1] + d1 + cvL*w1);
                float t2 = tanh_apx(cc[2] + d0 + cvH*w0);
                float t3 = tanh_apx(cc[3] + d1 + cvH*w1);
                rsum[mt*2]   += t0*v0 + t1*v1;
                rsum[mt*2+1] += t2*v0 + t3*v1;
            }
        }
    }

    // quad reduce (lanes sharing a row), accumulate per-row over warpN via smem atomics
#pragma unroll
    for (int j = 0; j < 4; ++j){
        float s = rsum[j];
        s += __shfl_xor_sync(0xffffffffu, s, 1);
        s += __shfl_xor_sync(0xffffffffu, s, 2);
        if ((lane & 3) == 0)
            atomicAdd(&sc_s[warpM*32 + (j>>1)*16 + (j&1)*8 + (lane>>2)], s);
    }
    __syncthreads();
    if (tid < BM) g_score[(size_t)b*NS + s0 + tid] = sc_s[tid];
}

// ---------------- kernel 3: masked softmax + coverage + zero context ----------------
__global__ void k_softmax(const float* __restrict__ mask, const float* __restrict__ cov,
                          float* __restrict__ out){
    const int b = blockIdx.x, tid = threadIdx.x;   // 32 blocks x 512 threads, 8 each
    __shared__ float red[512];
    const float* sc = g_score + (size_t)b*NS;
    float loc[8];
    float mx = -3.0e38f;
#pragma unroll
    for (int j = 0; j < 8; ++j){
        loc[j] = sc[tid + j*512];
        mx = fmaxf(mx, loc[j]);
    }
    red[tid] = mx; __syncthreads();
    for (int o = 256; o > 0; o >>= 1){
        if (tid < o) red[tid] = fmaxf(red[tid], red[tid+o]);
        __syncthreads();
    }
    mx = red[0];
    __syncthreads();
    float sum = 0.f;
#pragma unroll
    for (int j = 0; j < 8; ++j){
        loc[j] = __expf(loc[j] - mx) * mask[(size_t)b*NS + tid + j*512];
        sum += loc[j];
    }
    red[tid] = sum; __syncthreads();
    for (int o = 256; o > 0; o >>= 1){
        if (tid < o) red[tid] += red[tid+o];
        __syncthreads();
    }
    const float inv = 1.f / red[0];
    float* attn = out + NB*ND;
    float* covo = out + NB*ND + NB*NS;
#pragma unroll
    for (int j = 0; j < 8; ++j){
        size_t idx = (size_t)b*NS + tid + j*512;
        float a = loc[j] * inv;
        attn[idx] = a;                 // softmax*mask, renormalized
        covo[idx] = cov[idx] + a;      // coverage_new
    }
    out[b*ND + tid] = 0.f;             // zero context slice (d_out is poisoned)
}

// ---------------- kernel 4: context[b,d] = sum_s attn[b,s]*enc[b,s,d] ----------------
__global__ void __launch_bounds__(512, 2)
k_context(const float* __restrict__ enc, float* __restrict__ out){
    const int b = blockIdx.y, scnk = blockIdx.x, tid = threadIdx.x;  // 8 s-chunks x 32 b
    __shared__ float a_s[512];
    const float* attn = out + NB*ND;
    a_s[tid] = attn[(size_t)b*NS + scnk*512 + tid];
    __syncthreads();
    const int d4 = tid & 127;          // float4 column
    const int sg = tid >> 7;           // 4 s-groups of 128
    const float4* e4 = reinterpret_cast<const float4*>(enc)
                     + ((size_t)(b*NS + scnk*512 + sg*128))*(ND/4) + d4;
    const float* aw = a_s + sg*128;
    float4 a0 = {0,0,0,0}, a1 = {0,0,0,0}, a2 = {0,0,0,0}, a3 = {0,0,0,0};
#pragma unroll 2
    for (int s = 0; s < 128; s += 4){
        float4 v0 = e4[(size_t)(s)  *(ND/4)];
        float4 v1 = e4[(size_t)(s+1)*(ND/4)];
        float4 v2 = e4[(size_t)(s+2)*(ND/4)];
        float4 v3 = e4[(size_t)(s+3)*(ND/4)];
        float w0 = aw[s], w1 = aw[s+1], w2 = aw[s+2], w3 = aw[s+3];
        a0.x += w0*v0.x; a0.y += w0*v0.y; a0.z += w0*v0.z; a0.w += w0*v0.w;
        a1.x += w1*v1.x; a1.y += w1*v1.y; a1.z += w1*v1.z; a1.w += w1*v1.w;
        a2.x += w2*v2.x; a2.y += w2*v2.y; a2.z += w2*v2.z; a2.w += w2*v2.w;
        a3.x += w3*v3.x; a3.y += w3*v3.y; a3.z += w3*v3.z; a3.w += w3*v3.w;
    }
    float* o = out + b*ND + d4*4;
    atomicAdd(o+0, (a0.x+a1.x)+(a2.x+a3.x));
    atomicAdd(o+1, (a0.y+a1.y)+(a2.y+a3.y));
    atomicAdd(o+2, (a0.z+a1.z)+(a2.z+a3.z));
    atomicAdd(o+3, (a0.w+a1.w)+(a2.w+a3.w));
}

extern "C" void kernel_launch(void* const* d_in, const int* in_sizes, int n_in,
                              void* d_out, int out_size){
    const float* enc  = (const float*)d_in[0];  // (B,S,D)
    const float* hdec = (const float*)d_in[1];  // (1,B,H)
    const float* cdec = (const float*)d_in[2];  // (1,B,H)
    const float* mask = (const float*)d_in[3];  // (B,S)
    const float* cov  = (const float*)d_in[4];  // (B,S)
    const float* Wh   = (const float*)d_in[5];  // (D,D)
    const float* Ws   = (const float*)d_in[6];  // (D,D)
    const float* Wsb  = (const float*)d_in[7];  // (D,)
    const float* wc   = (const float*)d_in[8];  // (D,)
    const float* vw   = (const float*)d_in[9];  // (D,)
    float* out = (float*)d_out;                 // [context(B,D) | attn(B,S) | coverage(B,S)]

    cudaFuncSetAttribute(k_score, cudaFuncAttributeMaxDynamicSharedMemorySize, SMEM_TOTAL);

    k_prep    <<<544, 512>>>(Wh, hdec, cdec, Ws, Wsb);
    k_score   <<<dim3(NS/BM, NB), 512, SMEM_TOTAL>>>(enc, cov, wc, vw);
    k_softmax <<<NB, 512>>>(mask, cov, out);
    k_context <<<dim3(8, NB), 512>>>(enc, out);
}

// round 15
// speedup vs baseline: 1.1053x; 1.1053x over previous
#include <cuda_runtime.h>
#include <cuda_bf16.h>
#include <cstdint>

#define NB 32
#define NS 4096
#define NH 256
#define ND 512
#define BM 128
#define CH 64                    // k-slice
#define NSL (ND/CH)              // 8 slices

#define ROWA 520                 // A smem row stride (elems): 512+8 pad -> ldmatrix conflict-free
#define ROWB 72                  // B smem row stride (elems): 64+8 pad -> ldmatrix conflict-free
#define SM_A_BYTES (BM*ROWA*2)           // 133120 (persistent, full K)
#define SM_B_BYTES (256*ROWB*2)          // 36864 per buffer (256 n-rows x 64 k)
#define OFF_A   0
#define OFF_B   (SM_A_BYTES)             // 133120 (16B aligned)
#define OFF_DEC (OFF_B + 2*SM_B_BYTES)   // 206848
#define OFF_WC  (OFF_DEC + ND*4)
#define OFF_V   (OFF_WC  + ND*4)
#define OFF_COV (OFF_V   + ND*4)
#define OFF_SC  (OFF_COV + BM*4)
#define SMEM_TOTAL (OFF_SC + BM*4)       // 214016 bytes

// scratch (no allocations allowed -> device globals)
__device__ float g_score[NB*NS];
__device__ float g_dec[NB*ND];
__device__ __align__(16) __nv_bfloat16 g_wh[ND*ND];

__device__ __forceinline__ float tanh_apx(float x){
    float y; asm("tanh.approx.f32 %0, %1;" : "=f"(y) : "f"(x)); return y;
}

// ---------------- kernel 1: prep (Wh->bf16 + dec_feat) ----------------
__global__ void k_prep(const float* __restrict__ wh, const float* __restrict__ hdec,
                       const float* __restrict__ cdec, const float* __restrict__ Ws,
                       const float* __restrict__ Wsb){
    if (blockIdx.x < 512){
        int i = blockIdx.x*512 + threadIdx.x;        // 512 blocks cover D*D
        g_wh[i] = __float2bfloat16(wh[i]);
    } else {
        int b = blockIdx.x - 512, e = threadIdx.x;   // 32 blocks x 512 threads
        __shared__ float st[ND];
        st[e] = (e < NH) ? hdec[b*NH + e] : cdec[b*NH + e - NH];
        __syncthreads();
        const float4* w4 = reinterpret_cast<const float4*>(Ws + (size_t)e*ND);
        float acc = 0.f;
#pragma unroll 16
        for (int d4 = 0; d4 < ND/4; ++d4){
            float4 w = w4[d4];
            acc += st[4*d4]*w.x + st[4*d4+1]*w.y + st[4*d4+2]*w.z + st[4*d4+3]*w.w;
        }
        g_dec[b*ND + e] = acc + Wsb[e];
    }
}

// ---------------- kernel 2: fused score GEMM (mma.sync, 8 warps, 64x64 tiles) ----------------
// score[b,s] = sum_e v[e]*tanh( (enc@Wh^T)[b,s,e] + dec[b,e] + cov[b,s]*wc[e] )
__global__ void __launch_bounds__(256, 1)
k_score(const float* __restrict__ enc, const float* __restrict__ cov,
        const float* __restrict__ wc, const float* __restrict__ vw){
    extern __shared__ char smem[];
    const int tid   = threadIdx.x;
    const int lane  = tid & 31;
    const int warp  = tid >> 5;
    const int warpM = warp >> 2;     // 0..1 (64 rows each)
    const int warpN = warp & 3;      // 0..3 (64 cols each of the 256-col pass)
    const int b  = blockIdx.y;
    const int s0 = blockIdx.x * BM;

    float* dec_s = (float*)(smem + OFF_DEC);
    float* wc_s  = (float*)(smem + OFF_WC);
    float* v_s   = (float*)(smem + OFF_V);
    float* cov_s = (float*)(smem + OFF_COV);
    float* sc_s  = (float*)(smem + OFF_SC);

#pragma unroll
    for (int j = 0; j < 2; ++j){
        int e = tid + j*256;
        dec_s[e] = g_dec[b*ND + e]; wc_s[e] = wc[e]; v_s[e] = vw[e];
    }
    if (tid < BM){ cov_s[tid] = cov[(size_t)b*NS + s0 + tid]; sc_s[tid] = 0.f; }

    const uint32_t aBase = (uint32_t)__cvta_generic_to_shared(smem + OFF_A);
    const uint32_t bBase = (uint32_t)__cvta_generic_to_shared(smem + OFF_B);
    const float4*  enc4  = reinterpret_cast<const float4*>(enc);

    // per-thread ldmatrix element offsets (m8n8.x4, both K-major)
    int aOff[4];
#pragma unroll
    for (int mt = 0; mt < 4; ++mt)
        aOff[mt] = (warpM*64 + mt*16 + (lane & 15))*ROWA + (lane >> 4)*8;
    int bOff[4];
#pragma unroll
    for (int np = 0; np < 4; ++np)
        bOff[np] = (warpN*64 + np*16 + ((lane >> 4) & 1)*8 + (lane & 7))*ROWB
                   + ((lane >> 3) & 1)*8;

    // ---- prologue: A slice 0 convert+STS; B(pass0, slice0) cp.async ----
    {
#pragma unroll
        for (int j = 0; j < 8; ++j){
            int idx = tid + j*256;
            int r = idx >> 4, q = idx & 15;
            float4 f = enc4[((size_t)(b*NS + s0 + r))*(ND/4) + q];
            __nv_bfloat162 lo = __floats2bfloat162_rn(f.x, f.y);
            __nv_bfloat162 hi = __floats2bfloat162_rn(f.z, f.w);
            uint2 u; u.x = *reinterpret_cast<uint32_t*>(&lo); u.y = *reinterpret_cast<uint32_t*>(&hi);
            *reinterpret_cast<uint2*>(smem + OFF_A + r*(ROWA*2) + q*8) = u;
        }
#pragma unroll
        for (int j = 0; j < 8; ++j){
            int cid = tid + j*256;
            int row = cid >> 3, chk = cid & 7;
            const __nv_bfloat16* src = g_wh + (size_t)row*ND + chk*8;
            uint32_t dst = bBase + row*(ROWB*2) + chk*16;
            asm volatile("cp.async.cg.shared.global [%0], [%1], 16;\n"
                         :: "r"(dst), "l"(src) : "memory");
        }
        asm volatile("cp.async.commit_group;\n" ::: "memory");
    }

    float rsum[8];
#pragma unroll
    for (int j = 0; j < 8; ++j) rsum[j] = 0.f;

#pragma unroll 1
    for (int pass = 0; pass < 2; ++pass){
        const int n0 = pass*256;
        float c[32][4];
#pragma unroll
        for (int t = 0; t < 32; ++t){ c[t][0]=0.f;c[t][1]=0.f;c[t][2]=0.f;c[t][3]=0.f; }

#pragma unroll 1
        for (int sl = 0; sl < NSL; ++sl){
            // issue B cp.async for next slice (wraps into pass 1's slice 0)
            const bool more = (pass == 0) || (sl < 7);
            if (more){
                int nn = (sl == 7) ? 256 : n0;
                int kk = (sl == 7) ? 0 : (sl + 1)*CH;
                uint32_t bufOff = ((sl + 1) & 1) * SM_B_BYTES;
#pragma unroll
                for (int j = 0; j < 8; ++j){
                    int cid = tid + j*256;
                    int row = cid >> 3, chk = cid & 7;
                    const __nv_bfloat16* src = g_wh + (size_t)(nn + row)*ND + kk + chk*8;
                    uint32_t dst = bBase + bufOff + row*(ROWB*2) + chk*16;
                    asm volatile("cp.async.cg.shared.global [%0], [%1], 16;\n"
                                 :: "r"(dst), "l"(src) : "memory");
                }
                asm volatile("cp.async.commit_group;\n" ::: "memory");
                asm volatile("cp.async.wait_group 1;\n" ::: "memory");
            } else {
                asm volatile("cp.async.wait_group 0;\n" ::: "memory");
            }
            __syncthreads();   // B slice sl ready; A slice sl ready

            // prefetch A slice sl+1 (pass 0 only): LDGs issue before the MMA block
            float4 apre[8];
            const bool aload = (pass == 0) && (sl < 7);
            if (aload){
#pragma unroll
                for (int j = 0; j < 8; ++j){
                    int idx = tid + j*256;
                    int r = idx >> 4, q = idx & 15;
                    apre[j] = enc4[((size_t)(b*NS + s0 + r))*(ND/4) + (sl+1)*16 + q];
                }
            }

            const uint32_t bBuf = bBase + (uint32_t)(sl & 1)*SM_B_BYTES;
#pragma unroll
            for (int k2 = 0; k2 < 4; ++k2){
                const int kkA = sl*CH + k2*16;
                uint32_t a[4][4], bb[4][4];
#pragma unroll
                for (int mt = 0; mt < 4; ++mt){
                    uint32_t addr = aBase + (uint32_t)(aOff[mt] + kkA)*2;
                    asm volatile("ldmatrix.sync.aligned.m8n8.x4.shared.b16 {%0,%1,%2,%3}, [%4];\n"
                        : "=r"(a[mt][0]), "=r"(a[mt][1]), "=r"(a[mt][2]), "=r"(a[mt][3])
                        : "r"(addr));
                }
#pragma unroll
                for (int np = 0; np < 4; ++np){
                    uint32_t addr = bBuf + (uint32_t)(bOff[np] + k2*16)*2;
                    asm volatile("ldmatrix.sync.aligned.m8n8.x4.shared.b16 {%0,%1,%2,%3}, [%4];\n"
                        : "=r"(bb[np][0]), "=r"(bb[np][1]), "=r"(bb[np][2]), "=r"(bb[np][3])
                        : "r"(addr));
                }
#pragma unroll
                for (int mt = 0; mt < 4; ++mt){
#pragma unroll
                    for (int nt = 0; nt < 8; ++nt){
                        float* cc = c[mt*8 + nt];
                        uint32_t b0 = bb[nt>>1][(nt&1)*2], b1 = bb[nt>>1][(nt&1)*2 + 1];
                        asm("mma.sync.aligned.m16n8k16.row.col.f32.bf16.bf16.f32 "
                            "{%0,%1,%2,%3}, {%4,%5,%6,%7}, {%8,%9}, {%0,%1,%2,%3};\n"
                            : "+f"(cc[0]), "+f"(cc[1]), "+f"(cc[2]), "+f"(cc[3])
                            : "r"(a[mt][0]), "r"(a[mt][1]), "r"(a[mt][2]), "r"(a[mt][3]),
                              "r"(b0), "r"(b1));
                    }
                }
            }

            if (aload){
#pragma unroll
                for (int j = 0; j < 8; ++j){
                    int idx = tid + j*256;
                    int r = idx >> 4, q = idx & 15;
                    __nv_bfloat162 lo = __floats2bfloat162_rn(apre[j].x, apre[j].y);
                    __nv_bfloat162 hi = __floats2bfloat162_rn(apre[j].z, apre[j].w);
                    uint2 u; u.x = *reinterpret_cast<uint32_t*>(&lo); u.y = *reinterpret_cast<uint32_t*>(&hi);
                    *reinterpret_cast<uint2*>(smem + OFF_A + r*(ROWA*2) + ((sl+1)*CH + q*4)*2) = u;
                }
            }
            __syncthreads();   // B buf (sl&1) free; A slice sl+1 visible
        }

        // ---- fused epilogue for this 256-col pass ----
        const int rq = lane >> 2;            // 0..7
        const int eq = (lane & 3)*2;
#pragma unroll
        for (int mt = 0; mt < 4; ++mt){
            int rlo = warpM*64 + mt*16 + rq;
            float cvL = cov_s[rlo], cvH = cov_s[rlo + 8];
#pragma unroll
            for (int nt = 0; nt < 8; ++nt){
                int e0 = n0 + warpN*64 + nt*8 + eq;
                float d0 = dec_s[e0], d1 = dec_s[e0+1];
                float w0 = wc_s[e0],  w1 = wc_s[e0+1];
                float v0 = v_s[e0],   v1 = v_s[e0+1];
                float* cc = c[mt*8 + nt];
                float t0 = tanh_apx(cc[0] + d0 + cvL*w0);
                float t1 = tanh_apx(cc[1] + d1 + cvL*w1);
                float t2 = tanh_apx(cc[2] + d0 + cvH*w0);
                float t3 = tanh_apx(cc[3] + d1 + cvH*w1);
                rsum[mt*2]   += t0*v0 + t1*v1;
                rsum[mt*2+1] += t2*v0 + t3*v1;
            }
        }
    }

    // quad reduce (lanes sharing a row), accumulate per-row over warpN via smem atomics
#pragma unroll
    for (int j = 0; j < 8; ++j){
        float s = rsum[j];
        s += __shfl_xor_sync(0xffffffffu, s, 1);
        s += __shfl_xor_sync(0xffffffffu, s, 2);
        if ((lane & 3) == 0)
            atomicAdd(&sc_s[warpM*64 + (j>>1)*16 + (j&1)*8 + (lane>>2)], s);
    }
    __syncthreads();
    if (tid < BM) g_score[(size_t)b*NS + s0 + tid] = sc_s[tid];
}

// ---------------- kernel 3: masked softmax + coverage + zero context ----------------
__global__ void k_softmax(const float* __restrict__ mask, const float* __restrict__ cov,
                          float* __restrict__ out){
    const int b = blockIdx.x, tid = threadIdx.x;   // 32 blocks x 512 threads, 8 each
    __shared__ float red[512];
    const float* sc = g_score + (size_t)b*NS;
    float loc[8];
    float mx = -3.0e38f;
#pragma unroll
    for (int j = 0; j < 8; ++j){
        loc[j] = sc[tid + j*512];
        mx = fmaxf(mx, loc[j]);
    }
    red[tid] = mx; __syncthreads();
    for (int o = 256; o > 0; o >>= 1){
        if (tid < o) red[tid] = fmaxf(red[tid], red[tid+o]);
        __syncthreads();
    }
    mx = red[0];
    __syncthreads();
    float sum = 0.f;
#pragma unroll
    for (int j = 0; j < 8; ++j){
        loc[j] = __expf(loc[j] - mx) * mask[(size_t)b*NS + tid + j*512];
        sum += loc[j];
    }
    red[tid] = sum; __syncthreads();
    for (int o = 256; o > 0; o >>= 1){
        if (tid < o) red[tid] += red[tid+o];
        __syncthreads();
    }
    const float inv = 1.f / red[0];
    float* attn = out + NB*ND;
    float* covo = out + NB*ND + NB*NS;
#pragma unroll
    for (int j = 0; j < 8; ++j){
        size_t idx = (size_t)b*NS + tid + j*512;
        float a = loc[j] * inv;
        attn[idx] = a;                 // softmax*mask, renormalized
        covo[idx] = cov[idx] + a;      // coverage_new
    }
    out[b*ND + tid] = 0.f;             // zero context slice (d_out is poisoned)
}

// ---------------- kernel 4: context[b,d] = sum_s attn[b,s]*enc[b,s,d] ----------------
__global__ void __launch_bounds__(512, 2)
k_context(const float* __restrict__ enc, float* __restrict__ out){
    const int b = blockIdx.y, scnk = blockIdx.x, tid = threadIdx.x;  // 8 s-chunks x 32 b
    __shared__ float a_s[512];
    const float* attn = out + NB*ND;
    a_s[tid] = attn[(size_t)b*NS + scnk*512 + tid];
    __syncthreads();
    const int d4 = tid & 127;          // float4 column
    const int sg = tid >> 7;           // 4 s-groups of 128
    const float4* e4 = reinterpret_cast<const float4*>(enc)
                     + ((size_t)(b*NS + scnk*512 + sg*128))*(ND/4) + d4;
    const float* aw = a_s + sg*128;
    float4 a0 = {0,0,0,0}, a1 = {0,0,0,0}, a2 = {0,0,0,0}, a3 = {0,0,0,0};
#pragma unroll 2
    for (int s = 0; s < 128; s += 4){
        float4 v0 = e4[(size_t)(s)  *(ND/4)];
        float4 v1 = e4[(size_t)(s+1)*(ND/4)];
        float4 v2 = e4[(size_t)(s+2)*(ND/4)];
        float4 v3 = e4[(size_t)(s+3)*(ND/4)];
        float w0 = aw[s], w1 = aw[s+1], w2 = aw[s+2], w3 = aw[s+3];
        a0.x += w0*v0.x; a0.y += w0*v0.y; a0.z += w0*v0.z; a0.w += w0*v0.w;
        a1.x += w1*v1.x; a1.y += w1*v1.y; a1.z += w1*v1.z; a1.w += w1*v1.w;
        a2.x += w2*v2.x; a2.y += w2*v2.y; a2.z += w2*v2.z; a2.w += w2*v2.w;
        a3.x += w3*v3.x; a3.y += w3*v3.y; a3.z += w3*v3.z; a3.w += w3*v3.w;
    }
    float* o = out + b*ND + d4*4;
    atomicAdd(o+0, (a0.x+a1.x)+(a2.x+a3.x));
    atomicAdd(o+1, (a0.y+a1.y)+(a2.y+a3.y));
    atomicAdd(o+2, (a0.z+a1.z)+(a2.z+a3.z));
    atomicAdd(o+3, (a0.w+a1.w)+(a2.w+a3.w));
}

extern "C" void kernel_launch(void* const* d_in, const int* in_sizes, int n_in,
                              void* d_out, int out_size){
    const float* enc  = (const float*)d_in[0];  // (B,S,D)
    const float* hdec = (const float*)d_in[1];  // (1,B,H)
    const float* cdec = (const float*)d_in[2];  // (1,B,H)
    const float* mask = (const float*)d_in[3];  // (B,S)
    const float* cov  = (const float*)d_in[4];  // (B,S)
    const float* Wh   = (const float*)d_in[5];  // (D,D)
    const float* Ws   = (const float*)d_in[6];  // (D,D)
    const float* Wsb  = (const float*)d_in[7];  // (D,)
    const float* wc   = (const float*)d_in[8];  // (D,)
    const float* vw   = (const float*)d_in[9];  // (D,)
    float* out = (float*)d_out;                 // [context(B,D) | attn(B,S) | coverage(B,S)]

    cudaFuncSetAttribute(k_score, cudaFuncAttributeMaxDynamicSharedMemorySize, SMEM_TOTAL);

    k_prep    <<<544, 512>>>(Wh, hdec, cdec, Ws, Wsb);
    k_score   <<<dim3(NS/BM, NB), 256, SMEM_TOTAL>>>(enc, cov, wc, vw);
    k_softmax <<<NB, 512>>>(mask, cov, out);
    k_context <<<dim3(8, NB), 512>>>(enc, out);
}